// round 4
// baseline (speedup 1.0000x reference)
#include <cuda_runtime.h>
#include <math.h>
#include <cstdint>

#define N_FILT  80
#define HALF    126     // folded taps k = 0..125 (k pairs with 250-k; k=125 is center)
#define SEQ     32000
#define BATCH   32
#define TI      256     // output positions per block
#define KC      9       // k-chunk (126 = 14*9)
#define NCHUNK  14
#define THREADS 320

// Folded filters, pre-duplicated into f32x2 lanes: g_filt[k][o] = (f, f).
// Center tap (k=125) stored pre-halved so the conv pair-sum is uniform.
__device__ float2 g_filt[HALF * N_FILT];

// ---------------------------------------------------------------------------
// Kernel A: build folded filters. One block per filter, 128 threads.
// sin/cos evaluated in double of the fp32-rounded argument (args reach ~6e6;
// matches libdevice __nv_sinf to ~ulp and is immune to --use_fast_math).
// ---------------------------------------------------------------------------
__global__ void gen_filters_kernel(const float* __restrict__ fb1,
                                   const float* __restrict__ fband) {
    const int o = blockIdx.x;
    const int k = threadIdx.x;          // tap index 0..125 (125 = center)
    const float two_pi = 6.2831853071795864769f;
    const float fs = 16000.0f;
    const float minf = 50.0f / fs;
    const float beg = fabsf(fb1[o]) + minf;
    const float end = beg + fabsf(fband[o]) + minf;

    float val = 0.0f;
    float bpv = -3.0e38f;
    if (k < HALF) {
        const int ti = 125 - k;         // t_right value (0 at center)
        if (ti == 0) {
            val = 2.0f * end - 2.0f * beg;
        } else {
            const float t  = (float)ti;
            const float ce = two_pi * (end * fs);
            const float cb = two_pi * (beg * fs);
            const float ae = ce * t;
            const float ab = cb * t;
            const float ye = (float)sin((double)ae) / ae;
            const float yb = (float)sin((double)ab) / ab;
            val = (2.0f * end) * ye - (2.0f * beg) * yb;
        }
        bpv = val;
    }
    // max over the 251-tap row == max over the symmetric 126 half
    __shared__ float red[128];
    red[threadIdx.x] = bpv;
    __syncthreads();
    for (int s = 64; s > 0; s >>= 1) {
        if (threadIdx.x < s)
            red[threadIdx.x] = fmaxf(red[threadIdx.x], red[threadIdx.x + s]);
        __syncthreads();
    }
    const float mx = red[0];
    if (k < HALF) {
        const float nk  = (float)k * (251.0f / 250.0f);   // linspace(0,251,251)[k]
        const float wa  = (two_pi * nk) / 251.0f;
        const float win = 0.54f - 0.46f * (float)cos((double)wa);
        float fv = (val / mx) * win;
        if (k == 125) fv *= 0.5f;       // center: conv pair-sum doubles it back
        g_filt[k * N_FILT + o] = make_float2(fv, fv);
    }
}

// ---------------------------------------------------------------------------
// Kernel B: symmetric conv as smem GEMM, 80 filters x 256 positions per block,
// software-pipelined over k-chunks: build(c+1) overlaps compute(c), ONE
// barrier per chunk. Thread tile: 4 filters x 16 positions, packed fp32x2.
// ---------------------------------------------------------------------------
__global__ void __launch_bounds__(THREADS, 2)
conv_kernel(const float* __restrict__ x, float* __restrict__ out) {
    __shared__ float2 sFd[2][KC * N_FILT]; // duplicated filter chunks (11520 B)
    __shared__ float  sX[512];             // x tile, TI + 250 used     (2048 B)
    __shared__ float  sP[2][KC * TI];      // pair sums [kk][i]        (18432 B)

    const int tid = threadIdx.x;
    const int b   = blockIdx.y;
    const int J0  = blockIdx.x * TI;
    const float* xb = x + (size_t)b * SEQ;

    // load x segment [J0-125, J0+TI+125) with zero padding
    for (int i = tid; i < TI + 250; i += THREADS) {
        const int g = J0 - 125 + i;
        sX[i] = (g >= 0 && g < SEQ) ? xb[g] : 0.0f;
    }

    const int fg = tid >> 4;    // 0..19 : filter group (4 filters)
    const int ig = tid & 15;    // 0..15 : interleaved position chunk base

    unsigned long long acc[4][8];   // [filter][position pair], fp32x2 each
#pragma unroll
    for (int f = 0; f < 4; ++f)
#pragma unroll
        for (int p = 0; p < 8; ++p) acc[f][p] = 0ULL;

    __syncthreads();    // sX ready (build reads it)

    // ---- build helper (inlined twice) ----
    auto build = [&](int c, int buf) {
        const int k0 = c * KC;
        for (int idx = tid; idx < KC * N_FILT; idx += THREADS)
            sFd[buf][idx] = g_filt[k0 * N_FILT + idx];
        for (int idx = tid; idx < KC * TI; idx += THREADS) {
            const int kk = idx >> 8;            // / TI
            const int i  = idx & (TI - 1);
            const int k  = k0 + kk;
            sP[buf][idx] = sX[i + k] + sX[i + 250 - k];
        }
    };

    build(0, 0);
    __syncthreads();

    for (int c = 0; c < NCHUNK; ++c) {
        const int cur = c & 1;
        // issue next chunk's build first: its LDS/STS latency and crossbar
        // work overlap the FFMA2 stream below (different buffer, no dep)
        if (c + 1 < NCHUNK) build(c + 1, cur ^ 1);

        const float2* __restrict__ fptr = &sFd[cur][fg * 4];
        const float*  __restrict__ pptr = &sP[cur][ig * 4];
#pragma unroll
        for (int kk = 0; kk < KC; ++kk) {
            // 4 duplicated filter coefs: 2 broadcast LDS.128
            const ulonglong2 fa =
                *reinterpret_cast<const ulonglong2*>(fptr + kk * N_FILT);
            const ulonglong2 fb =
                *reinterpret_cast<const ulonglong2*>(fptr + kk * N_FILT + 2);
            // 16 positions as 8 packed pairs (4 interleaved float4 chunks)
            unsigned long long pp[8];
#pragma unroll
            for (int j = 0; j < 4; ++j) {
                const ulonglong2 pv = *reinterpret_cast<const ulonglong2*>(
                    pptr + kk * TI + 64 * j);
                pp[2 * j]     = pv.x;
                pp[2 * j + 1] = pv.y;
            }
            // 32 packed FMAs = 64 fp32 FMA lanes
#pragma unroll
            for (int p = 0; p < 8; ++p) {
                asm("fma.rn.f32x2 %0, %1, %2, %0;" : "+l"(acc[0][p]) : "l"(fa.x), "l"(pp[p]));
                asm("fma.rn.f32x2 %0, %1, %2, %0;" : "+l"(acc[1][p]) : "l"(fa.y), "l"(pp[p]));
                asm("fma.rn.f32x2 %0, %1, %2, %0;" : "+l"(acc[2][p]) : "l"(fb.x), "l"(pp[p]));
                asm("fma.rn.f32x2 %0, %1, %2, %0;" : "+l"(acc[3][p]) : "l"(fb.y), "l"(pp[p]));
            }
        }
        __syncthreads();    // compute(c) done everywhere; buf cur may be rebuilt
    }

    // epilogue: unpack and store (float4, coalesced in 16B-interleaved chunks)
#pragma unroll
    for (int f = 0; f < 4; ++f) {
        const int o = fg * 4 + f;
        float* op = out + (size_t)(b * N_FILT + o) * SEQ + J0;
#pragma unroll
        for (int j = 0; j < 4; ++j) {
            float4 v;
            asm("mov.b64 {%0, %1}, %2;" : "=f"(v.x), "=f"(v.y) : "l"(acc[f][2 * j]));
            asm("mov.b64 {%0, %1}, %2;" : "=f"(v.z), "=f"(v.w) : "l"(acc[f][2 * j + 1]));
            *reinterpret_cast<float4*>(op + (ig + 16 * j) * 4) = v;
        }
    }
}

// ---------------------------------------------------------------------------
extern "C" void kernel_launch(void* const* d_in, const int* in_sizes, int n_in,
                              void* d_out, int out_size) {
    const float* x     = (const float*)d_in[0];
    const float* fb1   = (const float*)d_in[1];
    const float* fband = (const float*)d_in[2];
    float* out = (float*)d_out;

    gen_filters_kernel<<<N_FILT, 128>>>(fb1, fband);
    conv_kernel<<<dim3(SEQ / TI, BATCH), THREADS>>>(x, out);
}

// round 7
// speedup vs baseline: 1.7368x; 1.7368x over previous
#include <cuda_runtime.h>
#include <math.h>
#include <cstdint>

#define SEQ      32000
#define NF       80
#define KF       128       // folded K: 126 real + 2 zero pad
#define MP       128       // positions per tile
#define TPB      8         // tiles per block
#define GRID     1000      // GRID*TPB = 8000 = 32 batches * 250 jtiles
#define NTHREADS 320       // 10 warps = 2 pos-halves x 5 filter stripes

// Folded filters, bf16 hi/lo splits, as u32 k-pairs: [split][o][kpair 0..63]
__device__ uint32_t g_Ff[2 * NF * (KF / 2)];

// smem: x window (384 f), P hi, P lo. P row stride 272 B -> bank-conflict-free
// A-fragment loads (bank = 4*(row%8) + (lane%4), all 32 distinct).
#define XW_OFF 0
#define PS     272
#define PH_OFF 1536
#define PL_OFF (PH_OFF + MP * PS)          // 1536 + 34816
#define SMEM_TOTAL (PL_OFF + MP * PS)      // 71168 B

#define MMA_BF16(d, a, bb)                                                  \
    asm volatile("mma.sync.aligned.m16n8k16.row.col.f32.bf16.bf16.f32 "     \
        "{%0,%1,%2,%3}, {%4,%5,%6,%7}, {%8,%9}, {%0,%1,%2,%3};"             \
        : "+f"((d)[0]), "+f"((d)[1]), "+f"((d)[2]), "+f"((d)[3])            \
        : "r"((a)[0]), "r"((a)[1]), "r"((a)[2]), "r"((a)[3]),               \
          "r"((bb)[0]), "r"((bb)[1]))

// ---------------------------------------------------------------------------
// Kernel A: build folded filters (center tap pre-halved), split to bf16
// hi/lo, store as u32 k-pairs. One block per filter, 128 threads.
// sin/cos in double of the fp32-rounded argument (fast-math immune).
// ---------------------------------------------------------------------------
__global__ void gen_filters_kernel(const float* __restrict__ fb1,
                                   const float* __restrict__ fband) {
    const int o = blockIdx.x;
    const int k = threadIdx.x;          // tap 0..125 (125 = center); 126..127 pad
    const float two_pi = 6.2831853071795864769f;
    const float fs = 16000.0f;
    const float minf = 50.0f / fs;
    const float beg = fabsf(fb1[o]) + minf;
    const float end = beg + fabsf(fband[o]) + minf;

    float val = 0.0f;
    float bpv = -3.0e38f;
    if (k < 126) {
        const int ti = 125 - k;
        if (ti == 0) {
            val = 2.0f * end - 2.0f * beg;
        } else {
            const float t  = (float)ti;
            const float ae = (two_pi * (end * fs)) * t;
            const float ab = (two_pi * (beg * fs)) * t;
            val = (2.0f * end) * ((float)sin((double)ae) / ae)
                - (2.0f * beg) * ((float)sin((double)ab) / ab);
        }
        bpv = val;
    }
    __shared__ float red[128];
    red[threadIdx.x] = bpv;
    __syncthreads();
    for (int s = 64; s > 0; s >>= 1) {
        if (threadIdx.x < s)
            red[threadIdx.x] = fmaxf(red[threadIdx.x], red[threadIdx.x + s]);
        __syncthreads();
    }
    const float mx = red[0];

    float fv = 0.0f;
    if (k < 126) {
        const float nk  = (float)k * (251.0f / 250.0f);
        const float wa  = (two_pi * nk) / 251.0f;
        const float win = 0.54f - 0.46f * (float)cos((double)wa);
        fv = (val / mx) * win;
        if (k == 125) fv *= 0.5f;       // center: P doubles it back
    }
    uint32_t hb, lb;
    asm("cvt.rn.bf16x2.f32 %0, %1, %2;" : "=r"(hb) : "f"(0.0f), "f"(fv));
    const float hi  = __uint_as_float(hb << 16);
    const float res = fv - hi;
    asm("cvt.rn.bf16x2.f32 %0, %1, %2;" : "=r"(lb) : "f"(0.0f), "f"(res));

    unsigned short* F16 = (unsigned short*)g_Ff;
    F16[o * KF + k]            = (unsigned short)(hb & 0xffffu);
    F16[(NF + o) * KF + k]     = (unsigned short)(lb & 0xffffu);
}

// ---------------------------------------------------------------------------
// Kernel B: folded conv as 3-term bf16-split HMMA GEMM.
// Per tile: D[128 pos, 80 filt] = Ph*Fh + Pl*Fh + Ph*Fl.
// Warp w: pos-half h=w/5 (64 rows), filter stripe s=w%5 (16 cols).
// B-fragments (filters) resident in registers across all TPB tiles.
// ---------------------------------------------------------------------------
extern __shared__ char smem[];

__global__ void __launch_bounds__(NTHREADS, 1)
conv_kernel(const float* __restrict__ x, float* __restrict__ out) {
    float* xw = (float*)(smem + XW_OFF);
    char*  Ph = smem + PH_OFF;
    char*  Pl = smem + PL_OFF;

    const int tid  = threadIdx.x;
    const int lane = tid & 31;
    const int warp = tid >> 5;
    const int h    = warp / 5;          // 0..1 position half
    const int s    = warp % 5;          // 0..4 filter stripe
    const int ln4  = lane >> 2;         // 0..7
    const int lm4  = lane & 3;          // 0..3

    // ---- load B fragments once: [split][ntile][kstep][reg] ----
    uint32_t bf[2][2][8][2];
#pragma unroll
    for (int sp = 0; sp < 2; ++sp)
#pragma unroll
        for (int nt = 0; nt < 2; ++nt)
#pragma unroll
            for (int ks = 0; ks < 8; ++ks) {
                const int n = s * 16 + nt * 8 + ln4;
                const uint32_t* Fp = g_Ff + (sp * NF + n) * (KF / 2) + ks * 8 + lm4;
                bf[sp][nt][ks][0] = Fp[0];
                bf[sp][nt][ks][1] = Fp[4];
            }

    for (int it = 0; it < TPB; ++it) {
        const int t  = blockIdx.x * TPB + it;
        const int b  = t / 250;
        const int J0 = (t % 250) * MP;

        __syncthreads();            // previous tile's P/xw fully consumed

        // 1) stage raw x window [J0-125, J0+253)
        const float* xb = x + (size_t)b * SEQ;
        for (int q = tid; q < 378; q += NTHREADS) {
            const int g = J0 - 125 + q;
            xw[q] = (g >= 0 && g < SEQ) ? xb[g] : 0.0f;
        }
        __syncthreads();

        // 2) build P hi/lo: P[j][k] = x[j+k] + x[j+250-k], k-pairs packed
        for (int idx = tid; idx < MP * 64; idx += NTHREADS) {
            const int j  = idx >> 6;
            const int kp = idx & 63;
            const int k  = kp * 2;
            float p0 = 0.0f, p1 = 0.0f;
            if (kp < 63) {
                p0 = xw[j + k]     + xw[j + 250 - k];
                p1 = xw[j + k + 1] + xw[j + 249 - k];
            }
            uint32_t hp;
            asm("cvt.rn.bf16x2.f32 %0, %1, %2;" : "=r"(hp) : "f"(p1), "f"(p0));
            const float h0 = __uint_as_float(hp << 16);
            const float h1 = __uint_as_float(hp & 0xffff0000u);
            const float r0 = p0 - h0, r1 = p1 - h1;
            uint32_t lp;
            asm("cvt.rn.bf16x2.f32 %0, %1, %2;" : "=r"(lp) : "f"(r1), "f"(r0));
            *(uint32_t*)(Ph + j * PS + kp * 4) = hp;
            *(uint32_t*)(Pl + j * PS + kp * 4) = lp;
        }
        __syncthreads();

        // 3) HMMA mainloop: 4 m-tiles x 2 n-tiles x 8 k-steps x 3 terms
        float acc[4][2][4];
#pragma unroll
        for (int mt = 0; mt < 4; ++mt)
#pragma unroll
            for (int nt = 0; nt < 2; ++nt)
#pragma unroll
                for (int r = 0; r < 4; ++r) acc[mt][nt][r] = 0.0f;

        const int rbase = h * 64 + ln4;
#pragma unroll
        for (int ks = 0; ks < 8; ++ks) {
            uint32_t ah[4][4], al[4][4];
#pragma unroll
            for (int mt = 0; mt < 4; ++mt) {
                const int row = rbase + mt * 16;
                const char* ph = Ph + row * PS + ks * 32 + lm4 * 4;
                const char* pl = Pl + row * PS + ks * 32 + lm4 * 4;
                ah[mt][0] = *(const uint32_t*)(ph);
                ah[mt][1] = *(const uint32_t*)(ph + 8 * PS);
                ah[mt][2] = *(const uint32_t*)(ph + 16);
                ah[mt][3] = *(const uint32_t*)(ph + 8 * PS + 16);
                al[mt][0] = *(const uint32_t*)(pl);
                al[mt][1] = *(const uint32_t*)(pl + 8 * PS);
                al[mt][2] = *(const uint32_t*)(pl + 16);
                al[mt][3] = *(const uint32_t*)(pl + 8 * PS + 16);
            }
#pragma unroll
            for (int mt = 0; mt < 4; ++mt)
#pragma unroll
                for (int nt = 0; nt < 2; ++nt) {
                    MMA_BF16(acc[mt][nt], ah[mt], bf[0][nt][ks]);  // Ph*Fh
                    MMA_BF16(acc[mt][nt], al[mt], bf[0][nt][ks]);  // Pl*Fh
                    MMA_BF16(acc[mt][nt], ah[mt], bf[1][nt][ks]);  // Ph*Fl
                }
        }

        // 4) epilogue: c0(r,o) c1(r,o+1) c2(r+8,o) c3(r+8,o+1)
#pragma unroll
        for (int mt = 0; mt < 4; ++mt) {
            const int rr = rbase + mt * 16;
#pragma unroll
            for (int nt = 0; nt < 2; ++nt) {
                const int o = s * 16 + nt * 8 + lm4 * 2;
                float* op = out + ((size_t)b * NF + o) * SEQ + J0;
                op[rr]           = acc[mt][nt][0];
                op[SEQ + rr]     = acc[mt][nt][1];
                op[rr + 8]       = acc[mt][nt][2];
                op[SEQ + rr + 8] = acc[mt][nt][3];
            }
        }
    }
}

// ---------------------------------------------------------------------------
extern "C" void kernel_launch(void* const* d_in, const int* in_sizes, int n_in,
                              void* d_out, int out_size) {
    const float* x     = (const float*)d_in[0];
    const float* fb1   = (const float*)d_in[1];
    const float* fband = (const float*)d_in[2];
    float* out = (float*)d_out;

    cudaFuncSetAttribute(conv_kernel,
                         cudaFuncAttributeMaxDynamicSharedMemorySize, SMEM_TOTAL);

    gen_filters_kernel<<<NF, 128>>>(fb1, fband);
    conv_kernel<<<GRID, NTHREADS, SMEM_TOTAL>>>(x, out);
}